// round 8
// baseline (speedup 1.0000x reference)
#include <cuda_runtime.h>
#include <cuda_fp16.h>
#include <cuda_bf16.h>

#define NN 51200
#define EE 1638400
#define GG 512
#define HCc 128
#define SLOPE 0.2f
#define GEMM_BLOCKS (NN / 64)   // 800

// ---------------- scratch (device globals; no allocation allowed) ----------------
__device__ __half2 g_xlh[NN * 64];       // xl in fp16, 64 half2 per node row
__device__ float   g_xr[NN * HCc];
__device__ float   g_h [NN * HCc];
__device__ int     g_deg[NN];            // zero-initialized; scan re-zeros after use
__device__ int     g_rowptr[NN + 1];
__device__ int     g_cursor[NN];
__device__ int     g_csr_src[EE];
__device__ float   g_pool[GG * HCc];
__device__ float   g_m1[GG * HCc];
__device__ float   g_m2[GG * HCc];

// ---------------- f32x2 packed helpers (sm_103a FFMA2) ----------------
__device__ __forceinline__ void ffma2(unsigned long long& d,
                                      unsigned long long a, unsigned long long b) {
    asm("fma.rn.f32x2 %0, %1, %2, %3;" : "=l"(d) : "l"(a), "l"(b), "l"(d));
}
__device__ __forceinline__ unsigned long long pack2(float v) {
    unsigned long long r;
    unsigned u = __float_as_uint(v);
    asm("mov.b64 %0, {%1, %1};" : "=l"(r) : "r"(u));
    return r;
}
__device__ __forceinline__ float lo2(unsigned long long v) { return __uint_as_float((unsigned)v); }
__device__ __forceinline__ float hi2(unsigned long long v) { return __uint_as_float((unsigned)(v >> 32)); }

__device__ __forceinline__ unsigned h2_bits(__half2 h) {
    __half2_raw r = *(__half2_raw*)&h;
    return ((unsigned)r.y << 16) | (unsigned)r.x;
}

// ---------------- dual GEMM body (FFMA2): xl(fp16) = in@Wl+bl ; xr = in@Wr+br ----------------
template <int DIN>
__device__ __forceinline__ void gemm_body(int bid,
                                 const float* __restrict__ in,
                                 const float* __restrict__ Wl, const float* __restrict__ bl,
                                 const float* __restrict__ Wr, const float* __restrict__ br) {
    constexpr int KT = (DIN < 32) ? DIN : 32;
    __shared__ __align__(16) float sW[KT * 264];   // [k][o], stride 264
    __shared__ __align__(16) float sIn[64 * 36];   // [node][k], stride 36

    const int tid  = threadIdx.x;
    const int part = tid & 15;
    const int ng   = tid >> 4;

    unsigned long long acc[4][4][2];   // [node][quad][pair]
#pragma unroll
    for (int j = 0; j < 4; j++)
#pragma unroll
        for (int c = 0; c < 4; c++) { acc[j][c][0] = 0ull; acc[j][c][1] = 0ull; }

    for (int kt = 0; kt < DIN; kt += KT) {
        for (int idx = tid; idx < KT * 256; idx += 256) {
            int k = idx >> 8;
            int o = idx & 255;
            float v = (o < 128) ? Wl[(kt + k) * 128 + o] : Wr[(kt + k) * 128 + (o - 128)];
            sW[k * 264 + o] = v;
        }
        for (int idx = tid; idx < 64 * KT; idx += 256) {
            int n = idx / KT;
            int k = idx - n * KT;
            sIn[n * 36 + k] = in[(bid * 64 + n) * DIN + kt + k];
        }
        __syncthreads();

#pragma unroll
        for (int k = 0; k < KT; k += 4) {
            unsigned long long ivp[4][4];
#pragma unroll
            for (int j = 0; j < 4; j++) {
                float4 iv = *(const float4*)&sIn[(ng * 4 + j) * 36 + k];
                ivp[j][0] = pack2(iv.x); ivp[j][1] = pack2(iv.y);
                ivp[j][2] = pack2(iv.z); ivp[j][3] = pack2(iv.w);
            }
#pragma unroll
            for (int kk = 0; kk < 4; kk++) {
#pragma unroll
                for (int c = 0; c < 4; c++) {
                    double2 wv = *(const double2*)&sW[(k + kk) * 264 + part * 4 + c * 64];
                    unsigned long long w01 = __double_as_longlong(wv.x);
                    unsigned long long w23 = __double_as_longlong(wv.y);
#pragma unroll
                    for (int j = 0; j < 4; j++) {
                        ffma2(acc[j][c][0], ivp[j][kk], w01);
                        ffma2(acc[j][c][1], ivp[j][kk], w23);
                    }
                }
            }
        }
        __syncthreads();
    }

    const int gn0 = bid * 64 + ng * 4;
#pragma unroll
    for (int j = 0; j < 4; j++) {
        const int node = gn0 + j;
#pragma unroll
        for (int c = 0; c < 4; c++) {
            const int o = part * 4 + c * 64;
            float4 v;
            v.x = lo2(acc[j][c][0]); v.y = hi2(acc[j][c][0]);
            v.z = lo2(acc[j][c][1]); v.w = hi2(acc[j][c][1]);
            if (c < 2) {
                v.x += bl[o]; v.y += bl[o + 1]; v.z += bl[o + 2]; v.w += bl[o + 3];
                __half2 h01 = __floats2half2_rn(v.x, v.y);
                __half2 h23 = __floats2half2_rn(v.z, v.w);
                unsigned long long pk = ((unsigned long long)h2_bits(h23) << 32)
                                        | (unsigned long long)h2_bits(h01);
                *(unsigned long long*)&g_xlh[node * 64 + o / 2] = pk;
            } else {
                const int o2 = o - 128;
                v.x += br[o2]; v.y += br[o2 + 1]; v.z += br[o2 + 2]; v.w += br[o2 + 3];
                *(float4*)&g_xr[node * 128 + o2] = v;
            }
        }
    }
}

// ---------------- fused: layer-1 GEMM (blocks 0..799) + degree histogram (800..2399) ----------------
__global__ __launch_bounds__(256) void fused_hist_gemm16(
                                 const int* __restrict__ dst, const float* __restrict__ x,
                                 const float* __restrict__ Wl, const float* __restrict__ bl,
                                 const float* __restrict__ Wr, const float* __restrict__ br) {
    if (blockIdx.x < GEMM_BLOCKS) {
        gemm_body<16>(blockIdx.x, x, Wl, bl, Wr, br);
    } else {
        const int4* d4 = (const int4*)dst;
        const int nthr = 1600 * 256;
        for (int e = (blockIdx.x - GEMM_BLOCKS) * 256 + threadIdx.x; e < EE / 4; e += nthr) {
            int4 v = d4[e];
            atomicAdd(&g_deg[v.x], 1);
            atomicAdd(&g_deg[v.y], 1);
            atomicAdd(&g_deg[v.z], 1);
            atomicAdd(&g_deg[v.w], 1);
        }
    }
}

__global__ __launch_bounds__(256) void dual_gemm128_kernel(
                                 const float* __restrict__ Wl, const float* __restrict__ bl,
                                 const float* __restrict__ Wr, const float* __restrict__ br) {
    gemm_body<128>(blockIdx.x, g_h, Wl, bl, Wr, br);
}

// ---------------- CSR scan (also re-zeros g_deg for the next replay) ----------------
// single block, 1024 threads, 50 elems each (1024*50 == 51200)
__global__ void scan_kernel() {
    __shared__ int ss[1024];
    const int t = threadIdx.x;
    const int base = t * 50;
    int s = 0;
#pragma unroll 5
    for (int j = 0; j < 50; j++) s += g_deg[base + j];
    ss[t] = s;
    __syncthreads();
    for (int off = 1; off < 1024; off <<= 1) {
        int v = (t >= off) ? ss[t - off] : 0;
        __syncthreads();
        ss[t] += v;
        __syncthreads();
    }
    int run = (t > 0) ? ss[t - 1] : 0;
    for (int j = 0; j < 50; j++) {
        int dv = g_deg[base + j];
        g_deg[base + j] = 0;           // reset for next graph replay
        g_rowptr[base + j] = run;
        g_cursor[base + j] = run;
        run += dv;
    }
    if (t == 1023) g_rowptr[NN] = run;
}

__global__ void scatter_kernel(const int* __restrict__ src, const int* __restrict__ dst) {
    const int4* s4 = (const int4*)src;
    const int4* d4 = (const int4*)dst;
    for (int e = blockIdx.x * blockDim.x + threadIdx.x; e < EE / 4; e += gridDim.x * blockDim.x) {
        int4 sv = s4[e];
        int4 dv = d4[e];
        g_csr_src[atomicAdd(&g_cursor[dv.x], 1)] = sv.x;
        g_csr_src[atomicAdd(&g_cursor[dv.y], 1)] = sv.y;
        g_csr_src[atomicAdd(&g_cursor[dv.z], 1)] = sv.z;
        g_csr_src[atomicAdd(&g_cursor[dv.w], 1)] = sv.w;
    }
}

// ---------------- fused GATv2 aggregation (one warp per dst node) ----------------
// max-free segment softmax; xl fp16; direct CSR index loads; 4 independent
// states; unconditional prefetch for full groups (branch-light main loop).
__device__ __forceinline__ void edge_update(const uint2 raw, const float4 xr4, const float4 at4,
                                            float& d, float4& acc) {
    float2 a01 = __half22float2(*(const __half2*)&raw.x);
    float2 a23 = __half22float2(*(const __half2*)&raw.y);
    float tx = a01.x + xr4.x; tx = fmaxf(tx, SLOPE * tx);
    float ty = a01.y + xr4.y; ty = fmaxf(ty, SLOPE * ty);
    float tz = a23.x + xr4.z; tz = fmaxf(tz, SLOPE * tz);
    float tw = a23.y + xr4.w; tw = fmaxf(tw, SLOPE * tw);
    float p = tx * at4.x + ty * at4.y + tz * at4.z + tw * at4.w;
    p += __shfl_xor_sync(0xffffffffu, p, 1);
    p += __shfl_xor_sync(0xffffffffu, p, 2);
    p += __shfl_xor_sync(0xffffffffu, p, 4);   // per-head score (8-lane groups)
    float w = __expf(p);
    d += w;
    acc.x = fmaf(w, a01.x, acc.x);
    acc.y = fmaf(w, a01.y, acc.y);
    acc.z = fmaf(w, a23.x, acc.z);
    acc.w = fmaf(w, a23.y, acc.w);
}

__global__ void gat_agg_kernel(const float* __restrict__ att, const float* __restrict__ bias) {
    const int warp = threadIdx.x >> 5;
    const int lane = threadIdx.x & 31;
    const int node = blockIdx.x * 8 + warp;

    const float4 xr4 = *(const float4*)(g_xr + node * 128 + lane * 4);
    const float4 at4 = *(const float4*)(att + lane * 4);
    const float4 b4  = *(const float4*)(bias + lane * 4);

    const int beg = g_rowptr[node];
    const int end = g_rowptr[node + 1];
    const int deg = end - beg;
    const int loff = lane * 2;

    float d0 = 0.f, d1 = 0.f, d2 = 0.f, d3 = 0.f;
    float4 acc0 = make_float4(0.f, 0.f, 0.f, 0.f);
    float4 acc1 = acc0, acc2 = acc0, acc3 = acc0;

    if (deg >= 4) {
        uint2 r0 = *(const uint2*)(g_xlh + g_csr_src[beg]     * 64 + loff);
        uint2 r1 = *(const uint2*)(g_xlh + g_csr_src[beg + 1] * 64 + loff);
        uint2 r2 = *(const uint2*)(g_xlh + g_csr_src[beg + 2] * 64 + loff);
        uint2 r3 = *(const uint2*)(g_xlh + g_csr_src[beg + 3] * 64 + loff);

        int k = beg;
        // main loop: next group fully in-range -> unconditional prefetch
        for (; k + 8 <= end; k += 4) {
            uint2 n0 = *(const uint2*)(g_xlh + g_csr_src[k + 4] * 64 + loff);
            uint2 n1 = *(const uint2*)(g_xlh + g_csr_src[k + 5] * 64 + loff);
            uint2 n2 = *(const uint2*)(g_xlh + g_csr_src[k + 6] * 64 + loff);
            uint2 n3 = *(const uint2*)(g_xlh + g_csr_src[k + 7] * 64 + loff);
            edge_update(r0, xr4, at4, d0, acc0);
            edge_update(r1, xr4, at4, d1, acc1);
            edge_update(r2, xr4, at4, d2, acc2);
            edge_update(r3, xr4, at4, d3, acc3);
            r0 = n0; r1 = n1; r2 = n2; r3 = n3;
        }
        // boundary group: 4 <= end-k <= 7
        const int rem = end - k - 4;   // 0..3 edges beyond this group
        uint2 n0 = make_uint2(0u, 0u), n1 = n0, n2 = n0;
        if (rem > 0) n0 = *(const uint2*)(g_xlh + g_csr_src[k + 4] * 64 + loff);
        if (rem > 1) n1 = *(const uint2*)(g_xlh + g_csr_src[k + 5] * 64 + loff);
        if (rem > 2) n2 = *(const uint2*)(g_xlh + g_csr_src[k + 6] * 64 + loff);
        edge_update(r0, xr4, at4, d0, acc0);
        edge_update(r1, xr4, at4, d1, acc1);
        edge_update(r2, xr4, at4, d2, acc2);
        edge_update(r3, xr4, at4, d3, acc3);
        if (rem > 0) edge_update(n0, xr4, at4, d0, acc0);
        if (rem > 1) edge_update(n1, xr4, at4, d1, acc1);
        if (rem > 2) edge_update(n2, xr4, at4, d2, acc2);
    } else {
        if (deg > 0) { uint2 r = *(const uint2*)(g_xlh + g_csr_src[beg]     * 64 + loff); edge_update(r, xr4, at4, d0, acc0); }
        if (deg > 1) { uint2 r = *(const uint2*)(g_xlh + g_csr_src[beg + 1] * 64 + loff); edge_update(r, xr4, at4, d1, acc1); }
        if (deg > 2) { uint2 r = *(const uint2*)(g_xlh + g_csr_src[beg + 2] * 64 + loff); edge_update(r, xr4, at4, d2, acc2); }
    }

    float dsum = (d0 + d1) + (d2 + d3);
    float4 acc;
    acc.x = (acc0.x + acc1.x) + (acc2.x + acc3.x);
    acc.y = (acc0.y + acc1.y) + (acc2.y + acc3.y);
    acc.z = (acc0.z + acc1.z) + (acc2.z + acc3.z);
    acc.w = (acc0.w + acc1.w) + (acc2.w + acc3.w);

    float inv = 1.f / (dsum + 1e-16f);
    float4 o;
    o.x = fmaxf(fmaf(acc.x, inv, b4.x), 0.f);
    o.y = fmaxf(fmaf(acc.y, inv, b4.y), 0.f);
    o.z = fmaxf(fmaf(acc.z, inv, b4.z), 0.f);
    o.w = fmaxf(fmaf(acc.w, inv, b4.w), 0.f);
    *(float4*)(g_h + node * 128 + lane * 4) = o;
}

// ---------------- global mean pool (batch is sorted) ----------------
__global__ void pool_kernel(const int* __restrict__ batch) {
    const int g = blockIdx.x;
    const int t = threadIdx.x;  // 128 threads
    __shared__ int sb, se;
    if (t == 0) {
        int lo = 0, hi = NN;
        while (lo < hi) { int mid = (lo + hi) >> 1; if (batch[mid] < g) lo = mid + 1; else hi = mid; }
        sb = lo;
        hi = NN;
        while (lo < hi) { int mid = (lo + hi) >> 1; if (batch[mid] < g + 1) lo = mid + 1; else hi = mid; }
        se = lo;
    }
    __syncthreads();
    float s0 = 0.f, s1 = 0.f, s2 = 0.f, s3 = 0.f;
    int n = sb;
    for (; n + 4 <= se; n += 4) {
        s0 += g_h[(n + 0) * 128 + t];
        s1 += g_h[(n + 1) * 128 + t];
        s2 += g_h[(n + 2) * 128 + t];
        s3 += g_h[(n + 3) * 128 + t];
    }
    for (; n < se; n++) s0 += g_h[n * 128 + t];
    float s = (s0 + s1) + (s2 + s3);
    int cnt = se - sb;
    g_pool[g * 128 + t] = s / (float)(cnt > 0 ? cnt : 1);
}

// ---------------- MLP head ----------------
__global__ void fc_bn_relu_kernel(int stage,
                                  const float* __restrict__ W, const float* __restrict__ b,
                                  const float* __restrict__ gamma, const float* __restrict__ beta) {
    const float* in = (stage == 0) ? g_pool : g_m1;
    float* out      = (stage == 0) ? g_m1   : g_m2;
    const int g = blockIdx.x, t = threadIdx.x;
    __shared__ float sin[128];
    sin[t] = in[g * 128 + t];
    __syncthreads();
    float a0 = b[t], a1 = 0.f;
#pragma unroll 4
    for (int k = 0; k < 128; k += 2) {
        a0 = fmaf(sin[k],     W[(k)     * 128 + t], a0);
        a1 = fmaf(sin[k + 1], W[(k + 1) * 128 + t], a1);
    }
    float a = a0 + a1;
    float scale = gamma[t] * rsqrtf(1.0f + 1e-5f);
    a = fmaxf(fmaf(a, scale, beta[t]), 0.f);
    out[g * 128 + t] = a;
}

__global__ void fc3_kernel(const float* __restrict__ W, const float* __restrict__ b,
                           float* __restrict__ out) {
    const int g = blockIdx.x, t = threadIdx.x;  // 128 threads
    __shared__ float sin[128];
    __shared__ float w0[4], w1[4];
    sin[t] = g_m2[g * 128 + t];
    __syncthreads();
    float p0 = sin[t] * W[t * 2 + 0];
    float p1 = sin[t] * W[t * 2 + 1];
#pragma unroll
    for (int off = 16; off; off >>= 1) {
        p0 += __shfl_xor_sync(0xffffffffu, p0, off);
        p1 += __shfl_xor_sync(0xffffffffu, p1, off);
    }
    if ((t & 31) == 0) { w0[t >> 5] = p0; w1[t >> 5] = p1; }
    __syncthreads();
    if (t == 0) out[g * 2 + 0] = w0[0] + w0[1] + w0[2] + w0[3] + b[0];
    if (t == 1) out[g * 2 + 1] = w1[0] + w1[1] + w1[2] + w1[3] + b[1];
}

// ---------------- launch ----------------
extern "C" void kernel_launch(void* const* d_in, const int* in_sizes, int n_in,
                              void* d_out, int out_size) {
    const float* x      = (const float*)d_in[0];
    const int*   ei     = (const int*)  d_in[1];
    const int*   batch  = (const int*)  d_in[2];
    const float* l1_Wl  = (const float*)d_in[3];
    const float* l1_bl  = (const float*)d_in[4];
    const float* l1_Wr  = (const float*)d_in[5];
    const float* l1_br  = (const float*)d_in[6];
    const float* l1_att = (const float*)d_in[7];
    const float* l1_bias= (const float*)d_in[8];
    const float* l2_Wl  = (const float*)d_in[9];
    const float* l2_bl  = (const float*)d_in[10];
    const float* l2_Wr  = (const float*)d_in[11];
    const float* l2_br  = (const float*)d_in[12];
    const float* l2_att = (const float*)d_in[13];
    const float* l2_bias= (const float*)d_in[14];
    const float* fc1_W  = (const float*)d_in[15];
    const float* fc1_b  = (const float*)d_in[16];
    const float* bn1_g  = (const float*)d_in[17];
    const float* bn1_b  = (const float*)d_in[18];
    const float* fc2_W  = (const float*)d_in[19];
    const float* fc2_b  = (const float*)d_in[20];
    const float* bn2_g  = (const float*)d_in[21];
    const float* bn2_b  = (const float*)d_in[22];
    const float* fc3_W  = (const float*)d_in[23];
    const float* fc3_b  = (const float*)d_in[24];

    const int* src = ei;
    const int* dst = ei + EE;
    float* out = (float*)d_out;

    // 1: layer-1 GEMM fused with degree histogram (independent work, overlapped)
    fused_hist_gemm16<<<GEMM_BLOCKS + 1600, 256>>>(dst, x, l1_Wl, l1_bl, l1_Wr, l1_br);
    // 2: prefix scan (also re-zeros g_deg for next replay)
    scan_kernel<<<1, 1024>>>();
    // 3: CSR scatter
    scatter_kernel<<<1600, 256>>>(src, dst);
    // 4: layer-1 aggregation  <- lands in the ncu-profiled launch slot
    gat_agg_kernel<<<NN / 8, 256>>>(l1_att, l1_bias);
    // 5-6: layer 2
    dual_gemm128_kernel<<<GEMM_BLOCKS, 256>>>(l2_Wl, l2_bl, l2_Wr, l2_br);
    gat_agg_kernel<<<NN / 8, 256>>>(l2_att, l2_bias);
    // 7-10: pool + MLP head
    pool_kernel<<<GG, 128>>>(batch);
    fc_bn_relu_kernel<<<GG, 128>>>(0, fc1_W, fc1_b, bn1_g, bn1_b);
    fc_bn_relu_kernel<<<GG, 128>>>(1, fc2_W, fc2_b, bn2_g, bn2_b);
    fc3_kernel<<<GG, 128>>>(fc3_W, fc3_b, out);
}

// round 9
// speedup vs baseline: 1.1114x; 1.1114x over previous
#include <cuda_runtime.h>
#include <cuda_fp16.h>
#include <cuda_bf16.h>

#define NN 51200
#define EE 1638400
#define GG 512
#define HCc 128
#define SLOPE 0.2f
#define GEMM_BLOCKS (NN / 64)   // 800

// ---------------- scratch (device globals; no allocation allowed) ----------------
__device__ __align__(16) __half2 g_xlh[NN * 64];   // xl fp16, 64 half2/row
__device__ __align__(16) __half2 g_xrh[NN * 64];   // xr fp16, 64 half2/row
__device__ float   g_h [NN * HCc];
__device__ int     g_deg[NN];            // zero-initialized; scan re-zeros after use
__device__ int     g_rowptr[NN + 1];
__device__ int     g_cursor[NN];
__device__ int     g_csr_src[EE];
__device__ float   g_pool[GG * HCc];
__device__ float   g_m1[GG * HCc];
__device__ float   g_m2[GG * HCc];

// ---------------- f32x2 packed helpers (sm_103a FFMA2) ----------------
__device__ __forceinline__ void ffma2(unsigned long long& d,
                                      unsigned long long a, unsigned long long b) {
    asm("fma.rn.f32x2 %0, %1, %2, %3;" : "=l"(d) : "l"(a), "l"(b), "l"(d));
}
__device__ __forceinline__ unsigned long long pack2(float v) {
    unsigned long long r;
    unsigned u = __float_as_uint(v);
    asm("mov.b64 %0, {%1, %1};" : "=l"(r) : "r"(u));
    return r;
}
__device__ __forceinline__ unsigned long long f2pack(float lo, float hi) {
    unsigned long long r;
    asm("mov.b64 %0, {%1, %2};" : "=l"(r) : "f"(lo), "f"(hi));
    return r;
}
__device__ __forceinline__ float lo2(unsigned long long v) { return __uint_as_float((unsigned)v); }
__device__ __forceinline__ float hi2(unsigned long long v) { return __uint_as_float((unsigned)(v >> 32)); }

__device__ __forceinline__ unsigned h2_bits(__half2 h) {
    __half2_raw r = *(__half2_raw*)&h;
    return ((unsigned)r.y << 16) | (unsigned)r.x;
}

// ---------------- dual GEMM body (FFMA2): xl,xr (both fp16) ----------------
template <int DIN>
__device__ __forceinline__ void gemm_body(int bid,
                                 const float* __restrict__ in,
                                 const float* __restrict__ Wl, const float* __restrict__ bl,
                                 const float* __restrict__ Wr, const float* __restrict__ br) {
    constexpr int KT = (DIN < 32) ? DIN : 32;
    __shared__ __align__(16) float sW[KT * 264];   // [k][o], stride 264
    __shared__ __align__(16) float sIn[64 * 36];   // [node][k], stride 36

    const int tid  = threadIdx.x;
    const int part = tid & 15;
    const int ng   = tid >> 4;

    unsigned long long acc[4][4][2];   // [node][quad][pair]
#pragma unroll
    for (int j = 0; j < 4; j++)
#pragma unroll
        for (int c = 0; c < 4; c++) { acc[j][c][0] = 0ull; acc[j][c][1] = 0ull; }

    for (int kt = 0; kt < DIN; kt += KT) {
        for (int idx = tid; idx < KT * 256; idx += 256) {
            int k = idx >> 8;
            int o = idx & 255;
            float v = (o < 128) ? Wl[(kt + k) * 128 + o] : Wr[(kt + k) * 128 + (o - 128)];
            sW[k * 264 + o] = v;
        }
        for (int idx = tid; idx < 64 * KT; idx += 256) {
            int n = idx / KT;
            int k = idx - n * KT;
            sIn[n * 36 + k] = in[(bid * 64 + n) * DIN + kt + k];
        }
        __syncthreads();

#pragma unroll
        for (int k = 0; k < KT; k += 4) {
            unsigned long long ivp[4][4];
#pragma unroll
            for (int j = 0; j < 4; j++) {
                float4 iv = *(const float4*)&sIn[(ng * 4 + j) * 36 + k];
                ivp[j][0] = pack2(iv.x); ivp[j][1] = pack2(iv.y);
                ivp[j][2] = pack2(iv.z); ivp[j][3] = pack2(iv.w);
            }
#pragma unroll
            for (int kk = 0; kk < 4; kk++) {
#pragma unroll
                for (int c = 0; c < 4; c++) {
                    double2 wv = *(const double2*)&sW[(k + kk) * 264 + part * 4 + c * 64];
                    unsigned long long w01 = __double_as_longlong(wv.x);
                    unsigned long long w23 = __double_as_longlong(wv.y);
#pragma unroll
                    for (int j = 0; j < 4; j++) {
                        ffma2(acc[j][c][0], ivp[j][kk], w01);
                        ffma2(acc[j][c][1], ivp[j][kk], w23);
                    }
                }
            }
        }
        __syncthreads();
    }

    const int gn0 = bid * 64 + ng * 4;
#pragma unroll
    for (int j = 0; j < 4; j++) {
        const int node = gn0 + j;
#pragma unroll
        for (int c = 0; c < 4; c++) {
            const int o = part * 4 + c * 64;
            float4 v;
            v.x = lo2(acc[j][c][0]); v.y = hi2(acc[j][c][0]);
            v.z = lo2(acc[j][c][1]); v.w = hi2(acc[j][c][1]);
            if (c < 2) {
                v.x += bl[o]; v.y += bl[o + 1]; v.z += bl[o + 2]; v.w += bl[o + 3];
                __half2 h01 = __floats2half2_rn(v.x, v.y);
                __half2 h23 = __floats2half2_rn(v.z, v.w);
                unsigned long long pk = ((unsigned long long)h2_bits(h23) << 32)
                                        | (unsigned long long)h2_bits(h01);
                *(unsigned long long*)&g_xlh[node * 64 + o / 2] = pk;
            } else {
                const int o2 = o - 128;
                v.x += br[o2]; v.y += br[o2 + 1]; v.z += br[o2 + 2]; v.w += br[o2 + 3];
                __half2 h01 = __floats2half2_rn(v.x, v.y);
                __half2 h23 = __floats2half2_rn(v.z, v.w);
                unsigned long long pk = ((unsigned long long)h2_bits(h23) << 32)
                                        | (unsigned long long)h2_bits(h01);
                *(unsigned long long*)&g_xrh[node * 64 + o2 / 2] = pk;
            }
        }
    }
}

// ---------------- fused: layer-1 GEMM (blocks 0..799) + degree histogram ----------------
__global__ __launch_bounds__(256) void fused_hist_gemm16(
                                 const int* __restrict__ dst, const float* __restrict__ x,
                                 const float* __restrict__ Wl, const float* __restrict__ bl,
                                 const float* __restrict__ Wr, const float* __restrict__ br) {
    if (blockIdx.x < GEMM_BLOCKS) {
        gemm_body<16>(blockIdx.x, x, Wl, bl, Wr, br);
    } else {
        const int4* d4 = (const int4*)dst;
        const int nthr = 1600 * 256;
        for (int e = (blockIdx.x - GEMM_BLOCKS) * 256 + threadIdx.x; e < EE / 4; e += nthr) {
            int4 v = d4[e];
            atomicAdd(&g_deg[v.x], 1);
            atomicAdd(&g_deg[v.y], 1);
            atomicAdd(&g_deg[v.z], 1);
            atomicAdd(&g_deg[v.w], 1);
        }
    }
}

__global__ __launch_bounds__(256) void dual_gemm128_kernel(
                                 const float* __restrict__ Wl, const float* __restrict__ bl,
                                 const float* __restrict__ Wr, const float* __restrict__ br) {
    gemm_body<128>(blockIdx.x, g_h, Wl, bl, Wr, br);
}

// ---------------- CSR scan (also re-zeros g_deg for the next replay) ----------------
__global__ void scan_kernel() {
    __shared__ int ss[1024];
    const int t = threadIdx.x;
    const int base = t * 50;
    int s = 0;
#pragma unroll 5
    for (int j = 0; j < 50; j++) s += g_deg[base + j];
    ss[t] = s;
    __syncthreads();
    for (int off = 1; off < 1024; off <<= 1) {
        int v = (t >= off) ? ss[t - off] : 0;
        __syncthreads();
        ss[t] += v;
        __syncthreads();
    }
    int run = (t > 0) ? ss[t - 1] : 0;
    for (int j = 0; j < 50; j++) {
        int dv = g_deg[base + j];
        g_deg[base + j] = 0;           // reset for next graph replay
        g_rowptr[base + j] = run;
        g_cursor[base + j] = run;
        run += dv;
    }
    if (t == 1023) g_rowptr[NN] = run;
}

__global__ void scatter_kernel(const int* __restrict__ src, const int* __restrict__ dst) {
    const int4* s4 = (const int4*)src;
    const int4* d4 = (const int4*)dst;
    for (int e = blockIdx.x * blockDim.x + threadIdx.x; e < EE / 4; e += gridDim.x * blockDim.x) {
        int4 sv = s4[e];
        int4 dv = d4[e];
        g_csr_src[atomicAdd(&g_cursor[dv.x], 1)] = sv.x;
        g_csr_src[atomicAdd(&g_cursor[dv.y], 1)] = sv.y;
        g_csr_src[atomicAdd(&g_cursor[dv.z], 1)] = sv.z;
        g_csr_src[atomicAdd(&g_cursor[dv.w], 1)] = sv.w;
    }
}

// ---------------- fused GATv2 aggregation: 4 edge-slots x 8 lanes per warp ----------------
// Each warp owns one dst node. lane = (slot<<3)|sub; slot s processes edges
// beg+s, beg+s+4, ... Lane's 16 channels = [sub*16, sub*16+16). Head = sub/2,
// so the per-head score reduce is ONE shfl_xor(1) (which also broadcasts).
// fp16 packed math for leakyrelu+dot (two accumulator chains), fp32 exp/denom,
// fp32x2 FFMA2 accumulation of w*a. Max-free softmax (scores bounded small).
__global__ __launch_bounds__(256) void gat_agg_kernel(const float* __restrict__ att,
                                                      const float* __restrict__ bias) {
    const int warp = threadIdx.x >> 5;
    const int lane = threadIdx.x & 31;
    const int slot = lane >> 3;
    const int sub  = lane & 7;
    const int node = blockIdx.x * 8 + warp;

    // xr (fp16) for this lane's 16 channels
    __half2 xr_h[8];
    {
        const uint4* xp = (const uint4*)g_xrh + node * 16 + sub * 2;
        *(uint4*)&xr_h[0] = xp[0];
        *(uint4*)&xr_h[4] = xp[1];
    }
    // att converted to fp16 (this lane's 16 channels)
    __half2 att_h[8];
    {
        const float4* ap = (const float4*)att + sub * 4;
        float4 A0 = ap[0], A1 = ap[1], A2 = ap[2], A3 = ap[3];
        att_h[0] = __floats2half2_rn(A0.x, A0.y); att_h[1] = __floats2half2_rn(A0.z, A0.w);
        att_h[2] = __floats2half2_rn(A1.x, A1.y); att_h[3] = __floats2half2_rn(A1.z, A1.w);
        att_h[4] = __floats2half2_rn(A2.x, A2.y); att_h[5] = __floats2half2_rn(A2.z, A2.w);
        att_h[6] = __floats2half2_rn(A3.x, A3.y); att_h[7] = __floats2half2_rn(A3.z, A3.w);
    }
    const __half2 slope2 = __float2half2_rn(SLOPE);

    const int beg = g_rowptr[node];
    const int end = g_rowptr[node + 1];
    const int iters = (end - beg + 3) >> 2;

    unsigned long long acc[8];
#pragma unroll
    for (int i = 0; i < 8; i++) acc[i] = 0ull;
    float d = 0.f;

    if (iters > 0) {
        const int safe = end - 1;
        const uint4* base = (const uint4*)g_xlh;
        int k = beg + slot;
        int idx = g_csr_src[min(k, safe)];
        uint4 ra = base[idx * 16 + sub * 2];
        uint4 rb = base[idx * 16 + sub * 2 + 1];
        for (int it = 0; it < iters; it++) {
            const bool valid = (k < end);
            const int kn = k + 4;
            const int idxn = g_csr_src[min(kn, safe)];
            const uint4 na = base[idxn * 16 + sub * 2];
            const uint4 nb = base[idxn * 16 + sub * 2 + 1];

            __half2 a[8];
            *(uint4*)&a[0] = ra;
            *(uint4*)&a[4] = rb;

            // leaky-relu(a+xr) dot att, in fp16 packed (two chains)
            __half2 pA, pB;
#pragma unroll
            for (int i = 0; i < 4; i++) {
                __half2 t = __hadd2(a[i], xr_h[i]);
                __half2 l = __hmax2(t, __hmul2(t, slope2));
                pA = (i == 0) ? __hmul2(l, att_h[0]) : __hfma2(l, att_h[i], pA);
            }
#pragma unroll
            for (int i = 4; i < 8; i++) {
                __half2 t = __hadd2(a[i], xr_h[i]);
                __half2 l = __hmax2(t, __hmul2(t, slope2));
                pB = (i == 4) ? __hmul2(l, att_h[4]) : __hfma2(l, att_h[i], pB);
            }
            __half2 pS = __hadd2(pA, pB);
            float p = __half2float(__hadd(__low2half(pS), __high2half(pS)));
            p += __shfl_xor_sync(0xffffffffu, p, 1);   // full head score, both lanes

            float w = valid ? __expf(p) : 0.f;
            d += w;
            unsigned long long wp = pack2(w);
#pragma unroll
            for (int i = 0; i < 8; i++) {
                float2 af = __half22float2(a[i]);
                unsigned long long au = f2pack(af.x, af.y);
                ffma2(acc[i], au, wp);
            }
            ra = na; rb = nb; k = kn;
        }
    }

    // merge the 4 slots (lanes differ in bits 3,4)
    float fx[8], fy[8];
#pragma unroll
    for (int i = 0; i < 8; i++) {
        float x = lo2(acc[i]), y = hi2(acc[i]);
        x += __shfl_xor_sync(0xffffffffu, x, 8);
        y += __shfl_xor_sync(0xffffffffu, y, 8);
        x += __shfl_xor_sync(0xffffffffu, x, 16);
        y += __shfl_xor_sync(0xffffffffu, y, 16);
        fx[i] = x; fy[i] = y;
    }
    d += __shfl_xor_sync(0xffffffffu, d, 8);
    d += __shfl_xor_sync(0xffffffffu, d, 16);

    if (slot == 0) {
        const float inv = 1.f / (d + 1e-16f);
        const float4* bp = (const float4*)bias + sub * 4;
        float* op = g_h + node * 128 + sub * 16;
#pragma unroll
        for (int q = 0; q < 4; q++) {
            float4 b = bp[q];
            float4 o;
            o.x = fmaxf(fmaf(fx[q * 2],     inv, b.x), 0.f);
            o.y = fmaxf(fmaf(fy[q * 2],     inv, b.y), 0.f);
            o.z = fmaxf(fmaf(fx[q * 2 + 1], inv, b.z), 0.f);
            o.w = fmaxf(fmaf(fy[q * 2 + 1], inv, b.w), 0.f);
            *(float4*)(op + q * 4) = o;
        }
    }
}

// ---------------- global mean pool (batch is sorted) ----------------
__global__ void pool_kernel(const int* __restrict__ batch) {
    const int g = blockIdx.x;
    const int t = threadIdx.x;  // 128 threads
    __shared__ int sb, se;
    if (t == 0) {
        int lo = 0, hi = NN;
        while (lo < hi) { int mid = (lo + hi) >> 1; if (batch[mid] < g) lo = mid + 1; else hi = mid; }
        sb = lo;
        hi = NN;
        while (lo < hi) { int mid = (lo + hi) >> 1; if (batch[mid] < g + 1) lo = mid + 1; else hi = mid; }
        se = lo;
    }
    __syncthreads();
    float s0 = 0.f, s1 = 0.f, s2 = 0.f, s3 = 0.f;
    int n = sb;
    for (; n + 4 <= se; n += 4) {
        s0 += g_h[(n + 0) * 128 + t];
        s1 += g_h[(n + 1) * 128 + t];
        s2 += g_h[(n + 2) * 128 + t];
        s3 += g_h[(n + 3) * 128 + t];
    }
    for (; n < se; n++) s0 += g_h[n * 128 + t];
    float s = (s0 + s1) + (s2 + s3);
    int cnt = se - sb;
    g_pool[g * 128 + t] = s / (float)(cnt > 0 ? cnt : 1);
}

// ---------------- MLP head ----------------
__global__ void fc_bn_relu_kernel(int stage,
                                  const float* __restrict__ W, const float* __restrict__ b,
                                  const float* __restrict__ gamma, const float* __restrict__ beta) {
    const float* in = (stage == 0) ? g_pool : g_m1;
    float* out      = (stage == 0) ? g_m1   : g_m2;
    const int g = blockIdx.x, t = threadIdx.x;
    __shared__ float sin[128];
    sin[t] = in[g * 128 + t];
    __syncthreads();
    float a0 = b[t], a1 = 0.f;
#pragma unroll 4
    for (int k = 0; k < 128; k += 2) {
        a0 = fmaf(sin[k],     W[(k)     * 128 + t], a0);
        a1 = fmaf(sin[k + 1], W[(k + 1) * 128 + t], a1);
    }
    float a = a0 + a1;
    float scale = gamma[t] * rsqrtf(1.0f + 1e-5f);
    a = fmaxf(fmaf(a, scale, beta[t]), 0.f);
    out[g * 128 + t] = a;
}

__global__ void fc3_kernel(const float* __restrict__ W, const float* __restrict__ b,
                           float* __restrict__ out) {
    const int g = blockIdx.x, t = threadIdx.x;  // 128 threads
    __shared__ float sin[128];
    __shared__ float w0[4], w1[4];
    sin[t] = g_m2[g * 128 + t];
    __syncthreads();
    float p0 = sin[t] * W[t * 2 + 0];
    float p1 = sin[t] * W[t * 2 + 1];
#pragma unroll
    for (int off = 16; off; off >>= 1) {
        p0 += __shfl_xor_sync(0xffffffffu, p0, off);
        p1 += __shfl_xor_sync(0xffffffffu, p1, off);
    }
    if ((t & 31) == 0) { w0[t >> 5] = p0; w1[t >> 5] = p1; }
    __syncthreads();
    if (t == 0) out[g * 2 + 0] = w0[0] + w0[1] + w0[2] + w0[3] + b[0];
    if (t == 1) out[g * 2 + 1] = w1[0] + w1[1] + w1[2] + w1[3] + b[1];
}

// ---------------- launch ----------------
extern "C" void kernel_launch(void* const* d_in, const int* in_sizes, int n_in,
                              void* d_out, int out_size) {
    const float* x      = (const float*)d_in[0];
    const int*   ei     = (const int*)  d_in[1];
    const int*   batch  = (const int*)  d_in[2];
    const float* l1_Wl  = (const float*)d_in[3];
    const float* l1_bl  = (const float*)d_in[4];
    const float* l1_Wr  = (const float*)d_in[5];
    const float* l1_br  = (const float*)d_in[6];
    const float* l1_att = (const float*)d_in[7];
    const float* l1_bias= (const float*)d_in[8];
    const float* l2_Wl  = (const float*)d_in[9];
    const float* l2_bl  = (const float*)d_in[10];
    const float* l2_Wr  = (const float*)d_in[11];
    const float* l2_br  = (const float*)d_in[12];
    const float* l2_att = (const float*)d_in[13];
    const float* l2_bias= (const float*)d_in[14];
    const float* fc1_W  = (const float*)d_in[15];
    const float* fc1_b  = (const float*)d_in[16];
    const float* bn1_g  = (const float*)d_in[17];
    const float* bn1_b  = (const float*)d_in[18];
    const float* fc2_W  = (const float*)d_in[19];
    const float* fc2_b  = (const float*)d_in[20];
    const float* bn2_g  = (const float*)d_in[21];
    const float* bn2_b  = (const float*)d_in[22];
    const float* fc3_W  = (const float*)d_in[23];
    const float* fc3_b  = (const float*)d_in[24];

    const int* src = ei;
    const int* dst = ei + EE;
    float* out = (float*)d_out;

    // 1: layer-1 GEMM fused with degree histogram
    fused_hist_gemm16<<<GEMM_BLOCKS + 1600, 256>>>(dst, x, l1_Wl, l1_bl, l1_Wr, l1_br);
    // 2: prefix scan (also re-zeros g_deg)
    scan_kernel<<<1, 1024>>>();
    // 3: CSR scatter
    scatter_kernel<<<1600, 256>>>(src, dst);
    // 4: layer-1 aggregation  <- ncu-profiled slot
    gat_agg_kernel<<<NN / 8, 256>>>(l1_att, l1_bias);
    // 5-6: layer 2
    dual_gemm128_kernel<<<GEMM_BLOCKS, 256>>>(l2_Wl, l2_bl, l2_Wr, l2_br);
    gat_agg_kernel<<<NN / 8, 256>>>(l2_att, l2_bias);
    // 7-10: pool + MLP head
    pool_kernel<<<GG, 128>>>(batch);
    fc_bn_relu_kernel<<<GG, 128>>>(0, fc1_W, fc1_b, bn1_g, bn1_b);
    fc_bn_relu_kernel<<<GG, 128>>>(1, fc2_W, fc2_b, bn2_g, bn2_b);
    fc3_kernel<<<GG, 128>>>(fc3_W, fc3_b, out);
}